// round 7
// baseline (speedup 1.0000x reference)
#include <cuda_runtime.h>
#include <math.h>

#define NN 50000
#define RPAD 50176
#define EE 800000
#define KH 20
#define SBLK 196          // ceil(NN/256)

// ---------------- scratch (device globals; zero-init at module load) ---------
__device__ float g_XL[(size_t)RPAD * 224];  // layer input/activations
__device__ float g_A0[(size_t)RPAD * 224];  // hop ping
__device__ float g_A1[(size_t)RPAD * 224];  // hop pong
__device__ float g_AC[(size_t)RPAD * 224];  // accumulator
__device__ float  g_deg[NN];
__device__ float  g_dis[NN];
__device__ int    g_cnt[NN];
__device__ int    g_rowptr[NN + 1];
__device__ int    g_cursor[NN];
__device__ int    g_bsum[256];
__device__ int    g_boff[256];
__device__ float2 g_cv[EE];

// ---------------- tf32 helpers ----------------
__device__ __forceinline__ void tfsplit(float v, float& h, float& l) {
    unsigned hu;
    asm("cvt.rna.tf32.f32 %0, %1;" : "=r"(hu) : "f"(v));
    h = __uint_as_float(hu);
    float r = v - h;
    unsigned lu;
    asm("cvt.rna.tf32.f32 %0, %1;" : "=r"(lu) : "f"(r));
    l = __uint_as_float(lu);
}
__device__ __forceinline__ void mma_tf32(float* c, const unsigned* a, const unsigned* b) {
    asm volatile(
        "mma.sync.aligned.m16n8k8.row.col.f32.tf32.tf32.f32 "
        "{%0,%1,%2,%3}, {%4,%5,%6,%7}, {%8,%9}, {%0,%1,%2,%3};"
        : "+f"(c[0]), "+f"(c[1]), "+f"(c[2]), "+f"(c[3])
        : "r"(a[0]), "r"(a[1]), "r"(a[2]), "r"(a[3]), "r"(b[0]), "r"(b[1]));
}

// ---------------- CSR build ----------------
__global__ void k_zero_nodes() {
    int i = blockIdx.x * blockDim.x + threadIdx.x;
    if (i < NN) { g_deg[i] = 0.f; g_cnt[i] = 0; }
}
__global__ void k_degcnt(const int* __restrict__ ei, const float* __restrict__ ew) {
    int e = blockIdx.x * blockDim.x + threadIdx.x;
    if (e < EE) {
        int d = ei[EE + e];
        atomicAdd(&g_deg[d], ew[e]);
        atomicAdd(&g_cnt[d], 1);
    }
}
__global__ void k_dis() {
    int i = blockIdx.x * blockDim.x + threadIdx.x;
    if (i < NN) {
        float d = g_deg[i];
        g_dis[i] = (d > 0.f) ? rsqrtf(d) : 0.f;
    }
}
__global__ void k_bsum() {
    __shared__ int sh[256];
    int t = threadIdx.x, i = blockIdx.x * 256 + t;
    sh[t] = (i < NN) ? g_cnt[i] : 0;
    __syncthreads();
    for (int o = 128; o; o >>= 1) {
        if (t < o) sh[t] += sh[t + o];
        __syncthreads();
    }
    if (!t) g_bsum[blockIdx.x] = sh[0];
}
__global__ void k_bscan() {
    __shared__ int sh[256];
    int t = threadIdx.x;
    int v = (t < SBLK) ? g_bsum[t] : 0;
    sh[t] = v;
    __syncthreads();
    for (int o = 1; o < 256; o <<= 1) {
        int u = (t >= o) ? sh[t - o] : 0;
        __syncthreads();
        sh[t] += u;
        __syncthreads();
    }
    if (t < SBLK) g_boff[t] = sh[t] - v;
}
__global__ void k_wptr() {
    __shared__ int sh[256];
    int t = threadIdx.x, i = blockIdx.x * 256 + t;
    int v = (i < NN) ? g_cnt[i] : 0;
    sh[t] = v;
    __syncthreads();
    for (int o = 1; o < 256; o <<= 1) {
        int u = (t >= o) ? sh[t - o] : 0;
        __syncthreads();
        sh[t] += u;
        __syncthreads();
    }
    int excl = sh[t] - v + g_boff[blockIdx.x];
    if (i < NN) {
        g_rowptr[i] = excl;
        g_cursor[i] = excl;
        if (i == NN - 1) g_rowptr[NN] = excl + v;
    }
}
__global__ void k_scatter(const int* __restrict__ ei, const float* __restrict__ ew) {
    int e = blockIdx.x * blockDim.x + threadIdx.x;
    if (e < EE) {
        int s = ei[e];
        int d = ei[EE + e];
        int p = atomicAdd(&g_cursor[d], 1);
        float2 cv;
        cv.x = __int_as_float(s);
        cv.y = g_dis[s] * ew[e] * g_dis[d];
        g_cv[p] = cv;
    }
}

// ---------------- vector propagation: warp/node, CH 32-wide chunks -----------
template <int CH>
__global__ void __launch_bounds__(256) k_prop(const float* __restrict__ hin,
                                              float* __restrict__ hout) {
    int w = (blockIdx.x * 256 + threadIdx.x) >> 5;
    if (w >= NN) return;
    int lane = threadIdx.x & 31;
    int beg = g_rowptr[w], end = g_rowptr[w + 1];
    const int S = CH * 32;
    float acc[CH];
#pragma unroll
    for (int t = 0; t < CH; ++t) acc[t] = 0.f;
    int p = beg;
    for (; p + 2 <= end; p += 2) {
        float2 cv0 = __ldg(&g_cv[p]);
        float2 cv1 = __ldg(&g_cv[p + 1]);
        const float* r0 = hin + (size_t)__float_as_int(cv0.x) * S + lane;
        const float* r1 = hin + (size_t)__float_as_int(cv1.x) * S + lane;
#pragma unroll
        for (int t = 0; t < CH; ++t) acc[t] += cv0.y * __ldg(r0 + 32 * t);
#pragma unroll
        for (int t = 0; t < CH; ++t) acc[t] += cv1.y * __ldg(r1 + 32 * t);
    }
    if (p < end) {
        float2 cv = __ldg(&g_cv[p]);
        const float* r = hin + (size_t)__float_as_int(cv.x) * S + lane;
#pragma unroll
        for (int t = 0; t < CH; ++t) acc[t] += cv.y * __ldg(r + 32 * t);
    }
    float* o = hout + (size_t)w * S + lane;
#pragma unroll
    for (int t = 0; t < CH; ++t) o[32 * t] = acc[t];
}

// ---------------- tensor-core GEMM: split-tf32 3-term, 128x64 tile ----------
// MODE 0: D = P      MODE 1: D += P      MODE 2: D2 = relu(D + P + bias)
#define BM 128
#define BN 64
#define BK 16
template <int MODE>
__global__ void __launch_bounds__(256) k_gemm_tc(const float* __restrict__ H, int sH, int Cin,
                                                 const float* __restrict__ W, int Cout,
                                                 float* __restrict__ D, int sD,
                                                 const float* __restrict__ bias,
                                                 float* __restrict__ D2, int sD2) {
    __shared__ float Ah[BK][BM + 8], Al[BK][BM + 8];
    __shared__ float Bh[BK][BN + 8], Bl[BK][BN + 8];
    int tid = threadIdx.x;
    int warp = tid >> 5, lane = tid & 31;
    int wm = warp >> 1, wn = warp & 1;      // 4(m) x 2(n) warp grid, warp tile 32x32
    int gid = lane >> 2, qid = lane & 3;
    int m0 = blockIdx.x * BM, n0 = blockIdx.y * BN;

    float acc[2][4][4];
#pragma unroll
    for (int mt = 0; mt < 2; ++mt)
#pragma unroll
        for (int nt = 0; nt < 4; ++nt)
#pragma unroll
            for (int i = 0; i < 4; ++i) acc[mt][nt][i] = 0.f;

    for (int k0 = 0; k0 < Cin; k0 += BK) {
        {   // A tile 128x16 fp32 load + tf32 split (rows zero-padded; tail cols
            // neutralized by B-guard zeros)
            int row = tid >> 2, kq = (tid & 3) * 4;
#pragma unroll
            for (int r = 0; r < 2; ++r) {
                int m = row + 64 * r;
                float4 v = *(const float4*)&H[(size_t)(m0 + m) * sH + k0 + kq];
                float h, l;
                tfsplit(v.x, h, l); Ah[kq + 0][m] = h; Al[kq + 0][m] = l;
                tfsplit(v.y, h, l); Ah[kq + 1][m] = h; Al[kq + 1][m] = l;
                tfsplit(v.z, h, l); Ah[kq + 2][m] = h; Al[kq + 2][m] = l;
                tfsplit(v.w, h, l); Ah[kq + 3][m] = h; Al[kq + 3][m] = l;
            }
        }
        {   // B tile 16x64, guarded both dims, split
#pragma unroll
            for (int e = tid; e < BK * BN; e += 256) {
                int k = e >> 6, n = e & 63;
                int gk = k0 + k, gn = n0 + n;
                float v = (gk < Cin && gn < Cout) ? __ldg(&W[(size_t)gk * Cout + gn]) : 0.f;
                float h, l;
                tfsplit(v, h, l);
                Bh[k][n] = h; Bl[k][n] = l;
            }
        }
        __syncthreads();
#pragma unroll
        for (int k8 = 0; k8 < 2; ++k8) {
            int kb = k8 * 8;
            unsigned ah[2][4], al[2][4];
#pragma unroll
            for (int mt = 0; mt < 2; ++mt) {
                int mr = wm * 32 + mt * 16 + gid;
                ah[mt][0] = __float_as_uint(Ah[kb + qid][mr]);
                ah[mt][1] = __float_as_uint(Ah[kb + qid][mr + 8]);
                ah[mt][2] = __float_as_uint(Ah[kb + qid + 4][mr]);
                ah[mt][3] = __float_as_uint(Ah[kb + qid + 4][mr + 8]);
                al[mt][0] = __float_as_uint(Al[kb + qid][mr]);
                al[mt][1] = __float_as_uint(Al[kb + qid][mr + 8]);
                al[mt][2] = __float_as_uint(Al[kb + qid + 4][mr]);
                al[mt][3] = __float_as_uint(Al[kb + qid + 4][mr + 8]);
            }
            unsigned bh[4][2], bl[4][2];
#pragma unroll
            for (int nt = 0; nt < 4; ++nt) {
                int nc = wn * 32 + nt * 8 + gid;
                bh[nt][0] = __float_as_uint(Bh[kb + qid][nc]);
                bh[nt][1] = __float_as_uint(Bh[kb + qid + 4][nc]);
                bl[nt][0] = __float_as_uint(Bl[kb + qid][nc]);
                bl[nt][1] = __float_as_uint(Bl[kb + qid + 4][nc]);
            }
#pragma unroll
            for (int mt = 0; mt < 2; ++mt)
#pragma unroll
                for (int nt = 0; nt < 4; ++nt) {
                    mma_tf32(acc[mt][nt], ah[mt], bh[nt]);
                    mma_tf32(acc[mt][nt], ah[mt], bl[nt]);
                    mma_tf32(acc[mt][nt], al[mt], bh[nt]);
                }
        }
        __syncthreads();
    }
    // epilogue: c0:(g,2q) c1:(g,2q+1) c2:(g+8,2q) c3:(g+8,2q+1)
#pragma unroll
    for (int mt = 0; mt < 2; ++mt) {
#pragma unroll
        for (int nt = 0; nt < 4; ++nt) {
#pragma unroll
            for (int i = 0; i < 4; ++i) {
                int gm = m0 + wm * 32 + mt * 16 + gid + ((i >> 1) ? 8 : 0);
                int gn = n0 + wn * 32 + nt * 8 + qid * 2 + (i & 1);
                if (gm >= NN || gn >= Cout) continue;
                float r = acc[mt][nt][i];
                if (MODE == 0) {
                    D[(size_t)gm * sD + gn] = r;
                } else if (MODE == 1) {
                    D[(size_t)gm * sD + gn] += r;
                } else {
                    float v = D[(size_t)gm * sD + gn] + r + bias[gn];
                    D2[(size_t)gm * sD2 + gn] = fmaxf(v, 0.f);
                }
            }
        }
    }
}

// ---------------- layer 1 (Cin=1): fused scalar prop + rank-1 update ----------
__global__ void __launch_bounds__(256) k_l1_out0(const float* __restrict__ x,
                                                 const float* __restrict__ W0,
                                                 const float* __restrict__ b) {
    int w = (blockIdx.x * 256 + threadIdx.x) >> 5;
    if (w >= NN) return;
    int lane = threadIdx.x & 31;
    float xv = x[w];
    g_AC[(size_t)w * 64 + lane] = xv * W0[lane] + b[lane];
    int c = lane + 32;
    if (c < 60) g_AC[(size_t)w * 64 + c] = xv * W0[c] + b[c];
}
__global__ void __launch_bounds__(256) k_l1_step(const float* __restrict__ hold,
                                                 float* __restrict__ hnew,
                                                 const float* __restrict__ Wk) {
    int w = (blockIdx.x * 256 + threadIdx.x) >> 5;
    if (w >= NN) return;
    int lane = threadIdx.x & 31;
    int beg = g_rowptr[w], end = g_rowptr[w + 1];
    float s = 0.f;
    for (int p = beg + lane; p < end; p += 32) {
        float2 cv = __ldg(&g_cv[p]);
        s += cv.y * __ldg(&hold[__float_as_int(cv.x)]);
    }
#pragma unroll
    for (int o = 16; o; o >>= 1) s += __shfl_xor_sync(0xffffffffu, s, o);
    if (lane == 0) hnew[w] = s;
    g_AC[(size_t)w * 64 + lane] += s * Wk[lane];
    int c = lane + 32;
    if (c < 60) g_AC[(size_t)w * 64 + c] += s * Wk[c];
}

// ---------------- layer 5 (Cout=1): fused scalar Horner step + GEMV -----------
__global__ void __launch_bounds__(256) k_l5(const float* __restrict__ X,
                                            const float* __restrict__ Wk,
                                            const float* __restrict__ told,
                                            float* __restrict__ tnew, int first) {
    int w = (blockIdx.x * 256 + threadIdx.x) >> 5;
    if (w >= NN) return;
    int lane = threadIdx.x & 31;
    float s = 0.f;
    if (!first) {
        int beg = g_rowptr[w], end = g_rowptr[w + 1];
        for (int p = beg + lane; p < end; p += 32) {
            float2 cv = __ldg(&g_cv[p]);
            s += cv.y * __ldg(&told[__float_as_int(cv.x)]);
        }
    }
    const float* xr = X + (size_t)w * 96;
    s += xr[lane] * Wk[lane] + xr[lane + 32] * Wk[lane + 32];
    if (lane < 16) s += xr[lane + 64] * Wk[lane + 64];
#pragma unroll
    for (int o = 16; o; o >>= 1) s += __shfl_xor_sync(0xffffffffu, s, o);
    if (lane == 0) tnew[w] = s;
}

// ---------------- misc ----------------
__global__ void __launch_bounds__(256) k_relu(const float* __restrict__ src, int si,
                                              float* __restrict__ dst, int so, int C) {
    int w = (blockIdx.x * 256 + threadIdx.x) >> 5;
    if (w >= NN) return;
    int lane = threadIdx.x & 31;
    for (int c = lane; c < C; c += 32)
        dst[(size_t)w * so + c] = fmaxf(src[(size_t)w * si + c], 0.f);
}
__global__ void k_sigmoid(const float* __restrict__ t, const float* __restrict__ b,
                          float* __restrict__ out) {
    int i = blockIdx.x * blockDim.x + threadIdx.x;
    if (i < NN) out[i] = 1.f / (1.f + expf(-(t[i] + b[0])));
}

// ---------------- host ----------------
extern "C" void kernel_launch(void* const* d_in, const int* in_sizes, int n_in,
                              void* d_out, int out_size) {
    const float* x  = (const float*)d_in[0];
    const int*   ei = (const int*)d_in[1];
    const float* ew = (const float*)d_in[2];
    const float* Wl[5]; const float* bl[5];
    for (int l = 0; l < 5; ++l) {
        Wl[l] = (const float*)d_in[3 + 2 * l];
        bl[l] = (const float*)d_in[4 + 2 * l];
    }
    float* out = (float*)d_out;

    float *XL, *A0, *A1, *AC;
    cudaGetSymbolAddress((void**)&XL, g_XL);
    cudaGetSymbolAddress((void**)&A0, g_A0);
    cudaGetSymbolAddress((void**)&A1, g_A1);
    cudaGetSymbolAddress((void**)&AC, g_AC);

    const int WG = (NN * 32 + 255) / 256;   // warp-per-node grid
    const int GM = RPAD / BM;               // 392 m-blocks

    // ---- CSR build (coalesced multi-block scan) ----
    k_zero_nodes<<<(NN + 255) / 256, 256>>>();
    k_degcnt<<<(EE + 255) / 256, 256>>>(ei, ew);
    k_dis<<<(NN + 255) / 256, 256>>>();
    k_bsum<<<SBLK, 256>>>();
    k_bscan<<<1, 256>>>();
    k_wptr<<<SBLK, 256>>>();
    k_scatter<<<(EE + 255) / 256, 256>>>(ei, ew);

    // ---- layer 1: Cin=1, Cout=60 — scalar prop + fused GEMV into AC(64) ----
    k_l1_out0<<<WG, 256>>>(x, Wl[0], bl[0]);
    {
        const float* hold = x;
        float* hnew = A0;
        for (int k = 1; k <= KH; ++k) {
            k_l1_step<<<WG, 256>>>(hold, hnew, Wl[0] + (size_t)k * 60);
            hold = hnew;
            hnew = (hnew == A0) ? A1 : A0;
        }
    }
    k_relu<<<WG, 256>>>(AC, 64, XL, 64, 60);

    // ---- layer 2: Cin=60 (S=64), Cout=100 — tensor GEMM, 2 n-blocks ----
    {
        dim3 g(GM, 2);
        k_gemm_tc<0><<<g, 256>>>(XL, 64, 60, Wl[1], 100, AC, 128, 0, 0, 0);
        const float* hin = XL;
        float* hop = A0;
        for (int k = 1; k <= KH; ++k) {
            k_prop<2><<<WG, 256>>>(hin, hop);
            const float* Wk = Wl[1] + (size_t)k * 6000;
            if (k < KH) k_gemm_tc<1><<<g, 256>>>(hop, 64, 60, Wk, 100, AC, 128, 0, 0, 0);
            else        k_gemm_tc<2><<<g, 256>>>(hop, 64, 60, Wk, 100, AC, 128,
                                                 bl[1], XL, 128);
            hin = hop;
            hop = (hop == A0) ? A1 : A0;
        }
    }

    // ---- layer 3: Cin=100 (S=128), Cout=200 — tensor GEMM, 4 n-blocks ----
    {
        dim3 g(GM, 4);
        k_gemm_tc<0><<<g, 256>>>(XL, 128, 100, Wl[2], 200, AC, 224, 0, 0, 0);
        const float* hin = XL;
        float* hop = A0;
        for (int k = 1; k <= KH; ++k) {
            k_prop<4><<<WG, 256>>>(hin, hop);
            const float* Wk = Wl[2] + (size_t)k * 20000;
            if (k < KH) k_gemm_tc<1><<<g, 256>>>(hop, 128, 100, Wk, 200, AC, 224, 0, 0, 0);
            else        k_gemm_tc<2><<<g, 256>>>(hop, 128, 100, Wk, 200, AC, 224,
                                                 bl[2], XL, 224);
            hin = hop;
            hop = (hop == A0) ? A1 : A0;
        }
    }

    // ---- layer 4: Cin=200, Cout=80 — Horner output space, 2 n-blocks ----
    {
        dim3 g(GM, 2);
        float* t = A0;
        float* o = A1;
        k_gemm_tc<0><<<g, 256>>>(XL, 224, 200, Wl[3] + (size_t)KH * 16000, 80, t, 96, 0, 0, 0);
        for (int k = KH - 1; k >= 1; --k) {
            k_prop<3><<<WG, 256>>>(t, o);
            k_gemm_tc<1><<<g, 256>>>(XL, 224, 200, Wl[3] + (size_t)k * 16000, 80, o, 96, 0, 0, 0);
            float* tmp = t; t = o; o = tmp;
        }
        k_prop<3><<<WG, 256>>>(t, o);
        k_gemm_tc<2><<<g, 256>>>(XL, 224, 200, Wl[3], 80, o, 96, bl[3], AC, 96);
    }

    // ---- layer 5: Cin=80 (X = AC stride 96), Cout=1 — fused Horner ----
    {
        float* tA = A0;
        float* tB = A1;
        k_l5<<<WG, 256>>>(AC, Wl[4] + (size_t)KH * 80, 0, tA, 1);
        const float* hold = tA;
        float* cur = tB;
        float* nxt = tA;
        for (int k = KH - 1; k >= 0; --k) {
            k_l5<<<WG, 256>>>(AC, Wl[4] + (size_t)k * 80, hold, cur, 0);
            hold = cur;
            float* tmp = cur; cur = nxt; nxt = tmp;
        }
        k_sigmoid<<<(NN + 255) / 256, 256>>>(hold, bl[4], out);
    }
}